// round 16
// baseline (speedup 1.0000x reference)
#include <cuda_runtime.h>
#include <cuda_fp16.h>
#include <math.h>
#include <stdint.h>

#define NN 2048
#define BB 256
#define DD 512
#define MAXIT 300

// ---- solve: 32 m x 4 n = 128 CTAs; W k<1216 resident; KC=64, NSTG=4 --------
#define SB 128
#define KC 64
#define NKC 32
#define NSTG 4
#define SUBB 8192                 // 64 rows x 128B
#define RES_SUB 19                // resident chunks (k<1216)
#define RESB (RES_SUB*SUBB)       // 152KB
#define STGB (2*SUBB)             // stage: A + B = 16KB
#define DYN_SMEM (RESB + NSTG*STGB + 128)

// ---- build_w tiling --------------------------------------------------------
#define WNSTG 3
#define WMAT (128*128)
#define WSTG (2*WMAT)
#define WDYN (WNSTG*WSTG + 128)
#define WKC 64
#define WNKC (NN/WKC)

__device__ __half  g_Wh[NN*NN];
__device__ __half  g_Ath[NN*NN];
__device__ float   g_Vx[NN*BB];
__device__ __half  g_zh[2][BB*NN];
__device__ float   g_ns[2][SB][2];   // per-CTA norm slots {d2,n2}, 2-phase
__device__ unsigned g_arrive, g_release;

__device__ __forceinline__ uint32_t smem_u32(const void* p) {
    uint32_t a;
    asm("{ .reg .u64 t; cvta.to.shared.u64 t, %1; cvt.u32.u64 %0, t; }" : "=r"(a) : "l"(p));
    return a;
}
__device__ __forceinline__ void cp16(uint32_t dst, const void* src) {
    asm volatile("cp.async.cg.shared.global [%0], [%1], 16;" :: "r"(dst), "l"(src) : "memory");
}
#define CP_COMMIT() asm volatile("cp.async.commit_group;" ::: "memory")
#define CP_WAIT(n)  asm volatile("cp.async.wait_group %0;" :: "n"(n) : "memory")
__device__ __forceinline__ void ldsm4(uint32_t* r, uint32_t a) {
    asm volatile("ldmatrix.sync.aligned.m8n8.x4.shared.b16 {%0,%1,%2,%3}, [%4];"
                 : "=r"(r[0]), "=r"(r[1]), "=r"(r[2]), "=r"(r[3]) : "r"(a));
}
__device__ __forceinline__ void mma_hf(float* c, const uint32_t* a, uint32_t b0, uint32_t b1) {
    asm volatile("mma.sync.aligned.m16n8k16.row.col.f32.f16.f16.f32 "
                 "{%0,%1,%2,%3}, {%4,%5,%6,%7}, {%8,%9}, {%0,%1,%2,%3};"
                 : "+f"(c[0]), "+f"(c[1]), "+f"(c[2]), "+f"(c[3])
                 : "r"(a[0]), "r"(a[1]), "r"(a[2]), "r"(a[3]), "r"(b0), "r"(b1));
}
__device__ __forceinline__ void sts_v4(uint32_t a, const float* v) {
    asm volatile("st.shared.v4.f32 [%0], {%1,%2,%3,%4};"
                 :: "r"(a), "f"(v[0]), "f"(v[1]), "f"(v[2]), "f"(v[3]) : "memory");
}
__device__ __forceinline__ void lds_v4(float* v, uint32_t a) {
    asm volatile("ld.shared.v4.f32 {%0,%1,%2,%3}, [%4];"
                 : "=f"(v[0]), "=f"(v[1]), "=f"(v[2]), "=f"(v[3]) : "r"(a));
}

__global__ void init_small() {
    if (threadIdx.x == 0) { g_arrive = 0u; g_release = 0u; }
}

// At[i][k] = A[k][i] in fp16, 64x64 tiles
__global__ void __launch_bounds__(256) split_at_kernel(const float* __restrict__ A) {
    __shared__ float t[64][65];
    const int i0 = blockIdx.x * 64, k0 = blockIdx.y * 64;
    const int lx = threadIdx.x & 63, ly = threadIdx.x >> 6;
#pragma unroll
    for (int r = 0; r < 64; r += 4)
        t[ly + r][lx] = A[(long)(k0 + ly + r) * NN + i0 + lx];
    __syncthreads();
#pragma unroll
    for (int r = 0; r < 64; r += 4)
        g_Ath[(long)(i0 + ly + r) * NN + k0 + lx] = __float2half_rn(t[lx][ly + r]);
}

// W = (1-m)I - At At^T + S - S^T  (fp16 mma), symmetric: only bi<=bj blocks.
__global__ void __launch_bounds__(256, 1) build_w_mma_kernel(const float* __restrict__ S,
                                                             const float* __restrict__ m_raw) {
    extern __shared__ __align__(16) char dsm[];
    const uint32_t sbase = (smem_u32(dsm) + 127u) & ~127u;
    const int tid = threadIdx.x, l = tid & 31, warp = tid >> 5;

    int bi = 0, rem = blockIdx.x;
    while (rem >= 16 - bi) { rem -= 16 - bi; bi++; }
    const int bj = bi + rem;
    const int i0 = bi * 128, j0 = bj * 128;

    const int wm = (warp >> 2) * 64, wn = (warp & 3) * 32;
    const int r7 = l & 7;
    const int rowA = wm + r7 + ((l >> 3) & 1) * 8;
    const int kgA = (l >> 4) & 1;
    const int rowBb = wn + r7 + ((l >> 4) & 1) * 8;
    const int kgB = (l >> 3) & 1;

    float c[4][4][4];
#pragma unroll
    for (int f = 0; f < 4; f++)
#pragma unroll
        for (int g = 0; g < 4; g++)
#pragma unroll
            for (int q = 0; q < 4; q++) c[f][g][q] = 0.0f;

#define W_LOAD(stg, k0v) do {                                                 \
    const uint32_t sb_ = sbase + (stg) * WSTG;                                \
    _Pragma("unroll")                                                         \
    for (int rep = 0; rep < 4; rep++) {                                       \
        const int idx_ = tid + rep * 256;                                     \
        const int r_ = idx_ >> 3, c_ = idx_ & 7;                              \
        const uint32_t d_ = (uint32_t)r_ * 128 + ((uint32_t)(c_ ^ (r_ & 7)) << 4); \
        cp16(sb_ + 0*WMAT + d_, g_Ath + (long)(i0 + r_) * NN + (k0v) + c_ * 8); \
        cp16(sb_ + 1*WMAT + d_, g_Ath + (long)(j0 + r_) * NN + (k0v) + c_ * 8); \
    } } while (0)

#pragma unroll
    for (int s = 0; s < WNSTG - 1; s++) { W_LOAD(s, s * WKC); CP_COMMIT(); }

    for (int kc = 0; kc < WNKC; kc++) {
        CP_WAIT(WNSTG - 2);
        __syncthreads();
        if (kc + WNSTG - 1 < WNKC) W_LOAD((kc + WNSTG - 1) % WNSTG, (kc + WNSTG - 1) * WKC);
        CP_COMMIT();
        const uint32_t sb = sbase + (kc % WNSTG) * WSTG;
#pragma unroll
        for (int s4 = 0; s4 < 4; s4++) {
            const int kg0 = s4 * 2;
            const uint32_t swA = (uint32_t)((kg0 + kgA) ^ r7) << 4;
            const uint32_t swB = (uint32_t)((kg0 + kgB) ^ r7) << 4;
            uint32_t ah[4][4], bh[2][4];
#pragma unroll
            for (int f = 0; f < 4; f++)
                ldsm4(ah[f], sb + 0*WMAT + (uint32_t)(rowA + f * 16) * 128 + swA);
#pragma unroll
            for (int g2 = 0; g2 < 2; g2++)
                ldsm4(bh[g2], sb + 1*WMAT + (uint32_t)(rowBb + g2 * 16) * 128 + swB);
#pragma unroll
            for (int f = 0; f < 4; f++)
#pragma unroll
                for (int g2 = 0; g2 < 2; g2++) {
                    mma_hf(c[f][g2*2+0], ah[f], bh[g2][0], bh[g2][1]);
                    mma_hf(c[f][g2*2+1], ah[f], bh[g2][2], bh[g2][3]);
                }
        }
    }
#undef W_LOAD

    const float m = log1pf(expf(m_raw[0]));
    const float omm = 1.0f - m;
#pragma unroll
    for (int f = 0; f < 4; f++)
#pragma unroll
        for (int g = 0; g < 4; g++)
#pragma unroll
            for (int h = 0; h < 2; h++) {
                const int i = i0 + wm + f * 16 + h * 8 + (l >> 2);
                const int j = j0 + wn + g * 8 + (l & 3) * 2;
                const float c0 = c[f][g][h*2+0], c1 = c[f][g][h*2+1];
                float2 sij = *(const float2*)&S[(long)i * NN + j];
                float w0 = -c0 + sij.x - S[(long)j * NN + i];
                float w1 = -c1 + sij.y - S[(long)(j + 1) * NN + i];
                if (i == j) w0 += omm;
                if (i == j + 1) w1 += omm;
                *(__half2*)&g_Wh[(long)i * NN + j] = __floats2half2_rn(w0, w1);
                if (bi != bj) {
                    g_Wh[(long)j * NN + i]       = __float2half_rn(-2.0f * c0 - w0);
                    g_Wh[(long)(j + 1) * NN + i] = __float2half_rn(-2.0f * c1 - w1);
                }
            }
}

// ---- build_vx: cp.async double-buffered, KTW=32 ----------------------------
#define TMW 64
#define KTW 32
#define VPAD 132          // 33 float4 per row-ish: 32 floats + 1 pad slot (in floats)
__global__ void __launch_bounds__(256) build_vx_kernel(const float* __restrict__ U,
                                                       const float* __restrict__ b,
                                                       const float* __restrict__ x) {
    // smem: Us/Xs, 2 buffers each: [2][64 rows][36 floats] (32 data + 4 pad)
    __shared__ __align__(16) float Us[2][TMW][36];
    __shared__ __align__(16) float Xs[2][TMW][36];
    const int i0 = blockIdx.x * TMW, j0 = blockIdx.y * TMW;
    const int tx = threadIdx.x & 15, ty = threadIdx.x >> 4;

    // loader: 64 rows x 8 float4 per matrix -> 512 cp16 / 256 threads = 2 each
    const int lr = threadIdx.x >> 2;           // 0..63
    const int lc = threadIdx.x & 3;            // 0..3 (float4 idx, +4 for second)

    float acc[4][4];
#pragma unroll
    for (int a = 0; a < 4; a++)
#pragma unroll
        for (int cc = 0; cc < 4; cc++) acc[a][cc] = 0.0f;

#define VX_LOAD(buf, k0v) do {                                                \
    cp16(smem_u32(&Us[buf][lr][lc * 4]),     U + (long)(i0 + lr) * DD + (k0v) + lc * 4);      \
    cp16(smem_u32(&Us[buf][lr][(lc+4) * 4]), U + (long)(i0 + lr) * DD + (k0v) + (lc+4) * 4);  \
    cp16(smem_u32(&Xs[buf][lr][lc * 4]),     x + (long)(j0 + lr) * DD + (k0v) + lc * 4);      \
    cp16(smem_u32(&Xs[buf][lr][(lc+4) * 4]), x + (long)(j0 + lr) * DD + (k0v) + (lc+4) * 4);  \
    } while (0)

    VX_LOAD(0, 0); CP_COMMIT();
    for (int s = 0; s < DD / KTW; s++) {
        CP_WAIT(0);
        __syncthreads();
        if (s + 1 < DD / KTW) VX_LOAD((s + 1) & 1, (s + 1) * KTW);
        CP_COMMIT();
        const int buf = s & 1;
#pragma unroll
        for (int k = 0; k < KTW; k++) {
            float4 av = *(const float4*)&Us[buf][ty * 4][k & 31];
            // gather row-major: need per-row k value; do scalar loads (4 rows x 4 cols)
            float am[4], bn[4];
#pragma unroll
            for (int q = 0; q < 4; q++) {
                am[q] = Us[buf][ty * 4 + q][k];
                bn[q] = Xs[buf][tx * 4 + q][k];
            }
#pragma unroll
            for (int mi = 0; mi < 4; mi++)
#pragma unroll
                for (int ni = 0; ni < 4; ni++) acc[mi][ni] += am[mi] * bn[ni];
        }
        __syncthreads();
    }
#undef VX_LOAD
#pragma unroll
    for (int mi = 0; mi < 4; mi++) {
        const int i = i0 + ty * 4 + mi;
        const float bi = b[i];
#pragma unroll
        for (int ni = 0; ni < 4; ni++)
            g_Vx[i * BB + j0 + tx * 4 + ni] = acc[mi][ni] + bi;
    }
}

__device__ __forceinline__ void grid_barrier(unsigned& gen) {
    __syncthreads();
    if (threadIdx.x == 0) {
        gen++;
        __threadfence();
        unsigned prev = atomicAdd(&g_arrive, 1u);
        if (prev == SB - 1) {
            atomicExch(&g_arrive, 0u);
            __threadfence();
            atomicExch(&g_release, gen);
        } else {
            while (*(volatile unsigned*)&g_release < gen) { }
            __threadfence();
        }
    }
    __syncthreads();
}

// ------ persistent fp16 solver: resident W(k<1216), KC=64 ring, slot norms --
__global__ void __launch_bounds__(256, 1) solve_kernel(float* __restrict__ out) {
    extern __shared__ __align__(16) char dsm[];
    const uint32_t sbase = (smem_u32(dsm) + 127u) & ~127u;
    __shared__ float sredD[8], sredN[8];
    __shared__ int s_stop;

    const int tid = threadIdx.x, l = tid & 31, warp = tid >> 5;
    const int i0 = (blockIdx.x >> 2) * 64, j0 = (blockIdx.x & 3) * 64;
    const int pm = (warp >> 1) & 1;
    const int pn = warp & 1;
    const int ks = warp >> 2;
    const int r7 = l & 7;
    const int rA8 = ((l >> 3) & 1) * 8, selA = (l >> 4) & 1;
    const int rB8 = ((l >> 4) & 1) * 8, selB = (l >> 3) & 1;
    const int rowA0 = pm * 32 + r7 + rA8;
    const int rowB0 = pn * 32 + r7 + rB8;

    // ---- resident W: rows i0..i0+63, k < 1216 (19 chunks of 8KB) ----
    for (int rep = 0; rep < 38; rep++) {
        const int idx = tid + rep * 256;          // 0..9727
        const int ch = idx >> 9;                  // chunk 0..18
        const int rem = idx & 511;
        const int r_ = rem >> 3, c_ = rem & 7;
        cp16(sbase + (uint32_t)ch * SUBB + (uint32_t)r_ * 128 +
                 ((uint32_t)(c_ ^ (r_ & 7)) << 4),
             g_Wh + (long)(i0 + r_) * NN + ch * KC + c_ * 8);
    }
    CP_COMMIT(); CP_WAIT(0); __syncthreads();

    const uint32_t O_RING = sbase + RESB;
    const int gk = ks * 2;

    float zr[2][2][2][2], vx[2][2][2][2];
#pragma unroll
    for (int f = 0; f < 2; f++)
#pragma unroll
        for (int gi = 0; gi < 2; gi++)
#pragma unroll
            for (int h = 0; h < 2; h++) {
                const int i = i0 + pm * 32 + f * 16 + h * 8 + (l >> 2);
                const int j = j0 + pn * 32 + (gk + gi) * 8 + (l & 3) * 2;
                float2 v = *(const float2*)&g_Vx[i * BB + j];
                vx[f][gi][h][0] = v.x; vx[f][gi][h][1] = v.y;
                zr[f][gi][h][0] = 0.0f; zr[f][gi][h][1] = 0.0f;
            }

    const int ld_r0 = tid >> 3, ld_c = tid & 7;
    const uint32_t ld_d0 = (uint32_t)ld_r0 * 128 + ((uint32_t)(ld_c ^ (ld_r0 & 7)) << 4);
    const int ld_r1 = ld_r0 + 32;
    const uint32_t ld_d1 = (uint32_t)ld_r1 * 128 + ((uint32_t)(ld_c ^ (ld_r1 & 7)) << 4);

#define STAGE_LOAD(kcn, zp) do {                                              \
    const int kn_ = (kcn);                                                    \
    const uint32_t st_ = O_RING + (uint32_t)((kn_) & (NSTG - 1)) * STGB;      \
    const int k0_ = kn_ * KC;                                                 \
    if (kn_ >= RES_SUB) {                                                     \
        cp16(st_ + ld_d0, g_Wh + (long)(i0 + ld_r0) * NN + k0_ + ld_c * 8);   \
        cp16(st_ + ld_d1, g_Wh + (long)(i0 + ld_r1) * NN + k0_ + ld_c * 8);   \
    }                                                                         \
    cp16(st_ + SUBB + ld_d0, (zp) + (long)(j0 + ld_r0) * NN + k0_ + ld_c * 8);\
    cp16(st_ + SUBB + ld_d1, (zp) + (long)(j0 + ld_r1) * NN + k0_ + ld_c * 8);\
    } while (0)

    unsigned gen = 0;
    int cur = 0, it = 0;

    while (1) {
        it++;
        const __half* __restrict__ zp = g_zh[cur];
        float c[2][4][4];
#pragma unroll
        for (int f = 0; f < 2; f++)
#pragma unroll
            for (int g = 0; g < 4; g++)
#pragma unroll
                for (int q = 0; q < 4; q++) c[f][g][q] = 0.0f;

        if (it > 1) {
#pragma unroll
            for (int s = 0; s < NSTG - 1; s++) { STAGE_LOAD(s, zp); CP_COMMIT(); }

            for (int kc = 0; kc < NKC; kc++) {
                CP_WAIT(NSTG - 2);
                __syncthreads();
                if (kc + NSTG - 1 < NKC) STAGE_LOAD(kc + NSTG - 1, zp);
                CP_COMMIT();

                const uint32_t rst = O_RING + (uint32_t)(kc & (NSTG - 1)) * STGB;
                const uint32_t abase = (kc < RES_SUB)
                    ? sbase + (uint32_t)kc * SUBB
                    : rst;
                const uint32_t bbase = rst + SUBB;
#pragma unroll
                for (int s4 = 0; s4 < 2; s4++) {
                    const int kg0 = (ks * 2 + s4) * 2;
                    const uint32_t swA = (uint32_t)((kg0 + selA) ^ r7) << 4;
                    const uint32_t swB = (uint32_t)((kg0 + selB) ^ r7) << 4;
                    uint32_t ah0[4], ah1[4], bh0[4], bh1[4];
                    ldsm4(ah0, abase + (uint32_t)rowA0 * 128 + swA);
                    ldsm4(ah1, abase + (uint32_t)(rowA0 + 16) * 128 + swA);
                    ldsm4(bh0, bbase + (uint32_t)rowB0 * 128 + swB);
                    ldsm4(bh1, bbase + (uint32_t)(rowB0 + 16) * 128 + swB);
                    mma_hf(c[0][0], ah0, bh0[0], bh0[1]);
                    mma_hf(c[0][1], ah0, bh0[2], bh0[3]);
                    mma_hf(c[0][2], ah0, bh1[0], bh1[1]);
                    mma_hf(c[0][3], ah0, bh1[2], bh1[3]);
                    mma_hf(c[1][0], ah1, bh0[0], bh0[1]);
                    mma_hf(c[1][1], ah1, bh0[2], bh0[3]);
                    mma_hf(c[1][2], ah1, bh1[0], bh1[1]);
                    mma_hf(c[1][3], ah1, bh1[2], bh1[3]);
                }
            }

            // ---- k-split partial exchange (ring reused as buffer) ----
            CP_WAIT(0);
            __syncthreads();
            const uint32_t myslot = O_RING +
                (uint32_t)((((warp & 3) * 2 + ks) * 32 + l)) * 64u;
            const uint32_t prslot = O_RING +
                (uint32_t)((((warp & 3) * 2 + (1 - ks)) * 32 + l)) * 64u;
            const int go = (1 - ks) * 2;
#pragma unroll
            for (int f = 0; f < 2; f++)
#pragma unroll
                for (int gi = 0; gi < 2; gi++)
                    sts_v4(myslot + (uint32_t)(f * 2 + gi) * 16u, c[f][go + gi]);
            __syncthreads();
#pragma unroll
            for (int f = 0; f < 2; f++)
#pragma unroll
                for (int gi = 0; gi < 2; gi++) {
                    float v[4];
                    lds_v4(v, prslot + (uint32_t)(f * 2 + gi) * 16u);
#pragma unroll
                    for (int q = 0; q < 4; q++) c[f][gk + gi][q] += v[q];
                }
        }

        // ---- epilogue ----
        __half* __restrict__ zn = g_zh[cur ^ 1];
        float d2 = 0.0f, n2 = 0.0f;
#pragma unroll
        for (int f = 0; f < 2; f++)
#pragma unroll
            for (int gi = 0; gi < 2; gi++)
#pragma unroll
                for (int h = 0; h < 2; h++) {
                    const int i = i0 + pm * 32 + f * 16 + h * 8 + (l >> 2);
                    const int j = j0 + pn * 32 + (gk + gi) * 8 + (l & 3) * 2;
#pragma unroll
                    for (int p = 0; p < 2; p++) {
                        const float zv = zr[f][gi][h][p];
                        float v = 0.9f * zv +
                                  0.1f * (c[f][gk + gi][h * 2 + p] + vx[f][gi][h][p]);
                        float r = v > 0.0f ? v : 0.0f;
                        zr[f][gi][h][p] = r;
                        zn[(j + p) * NN + i] = __float2half_rn(r);
                        const float dd = r - zv;
                        d2 += dd * dd;
                        n2 += zv * zv;
                    }
                }
#pragma unroll
        for (int off = 16; off; off >>= 1) {
            d2 += __shfl_xor_sync(0xffffffffu, d2, off);
            n2 += __shfl_xor_sync(0xffffffffu, n2, off);
        }
        if (l == 0) { sredD[warp] = d2; sredN[warp] = n2; }
        __syncthreads();
        const int ph = it & 1;
        if (tid == 0) {
            float Dd = 0.0f, Nd = 0.0f;
#pragma unroll
            for (int w = 0; w < 8; w++) { Dd += sredD[w]; Nd += sredN[w]; }
            g_ns[ph][blockIdx.x][0] = Dd;
            g_ns[ph][blockIdx.x][1] = Nd;
        }

        grid_barrier(gen);

        // ---- slot reduction: every CTA computes the stop decision ----
        {
            float d2s = 0.0f, n2s = 0.0f;
            if (tid < SB) {
                float2 sv = *(const float2*)&g_ns[ph][tid][0];
                d2s = sv.x; n2s = sv.y;
            }
#pragma unroll
            for (int off = 16; off; off >>= 1) {
                d2s += __shfl_xor_sync(0xffffffffu, d2s, off);
                n2s += __shfl_xor_sync(0xffffffffu, n2s, off);
            }
            if (l == 0) { sredD[warp] = d2s; sredN[warp] = n2s; }
            __syncthreads();
            if (tid == 0) {
                float Dt = 0.0f, Nt = 0.0f;
#pragma unroll
                for (int w = 0; w < 4; w++) { Dt += sredD[w]; Nt += sredN[w]; }
                const float err = sqrtf(Dt) / (sqrtf(Nt) + 1e-12f);
                s_stop = (it >= MAXIT || err < 1e-4f) ? 1 : 0;
            }
            __syncthreads();
        }
        cur ^= 1;
        if (s_stop) break;
    }
#undef STAGE_LOAD

#pragma unroll
    for (int f = 0; f < 2; f++)
#pragma unroll
        for (int gi = 0; gi < 2; gi++)
#pragma unroll
            for (int h = 0; h < 2; h++) {
                const int i = i0 + pm * 32 + f * 16 + h * 8 + (l >> 2);
                const int j = j0 + pn * 32 + (gk + gi) * 8 + (l & 3) * 2;
                float2 v;
                v.x = zr[f][gi][h][0];
                v.y = zr[f][gi][h][1];
                *(float2*)&out[i * BB + j] = v;
            }
}

extern "C" void kernel_launch(void* const* d_in, const int* in_sizes, int n_in,
                              void* d_out, int out_size) {
    const float* A     = (const float*)d_in[0];
    const float* S     = (const float*)d_in[1];
    const float* m_raw = (const float*)d_in[2];
    const float* U     = (const float*)d_in[3];
    const float* b     = (const float*)d_in[4];
    const float* x     = (const float*)d_in[5];
    float* out = (float*)d_out;

    cudaFuncSetAttribute(solve_kernel, cudaFuncAttributeMaxDynamicSharedMemorySize, DYN_SMEM);
    cudaFuncSetAttribute(build_w_mma_kernel, cudaFuncAttributeMaxDynamicSharedMemorySize, WDYN);

    init_small<<<1, 32>>>();
    dim3 gt(NN / 64, NN / 64);
    split_at_kernel<<<gt, 256>>>(A);
    build_w_mma_kernel<<<136, 256, WDYN>>>(S, m_raw);
    dim3 gv(NN / TMW, BB / TMW);
    build_vx_kernel<<<gv, 256>>>(U, b, x);
    solve_kernel<<<SB, 256, DYN_SMEM>>>(out);
}

// round 17
// speedup vs baseline: 1.2077x; 1.2077x over previous
#include <cuda_runtime.h>
#include <cuda_fp16.h>
#include <math.h>
#include <stdint.h>

#define NN 2048
#define BB 256
#define DD 512
#define MAXIT 300

// ---- solve: 32 m x 4 n = 128 CTAs; W k<1152 resident; KC=64, NSTG=5 --------
#define SB 128
#define KC 64
#define NKC 32
#define NSTG 5
#define SUBB 8192                 // 64 rows x 128B
#define RES_SUB 18                // resident chunks (k<1152)
#define RESB (RES_SUB*SUBB)       // 144KB
#define STGB (2*SUBB)             // stage: A + B = 16KB
#define DYN_SMEM (RESB + NSTG*STGB + 128)

// ---- build_w tiling --------------------------------------------------------
#define WNSTG 3
#define WMAT (128*128)
#define WSTG (2*WMAT)
#define WDYN (WNSTG*WSTG + 128)
#define WKC 64
#define WNKC (NN/WKC)

__device__ __half  g_Wh[NN*NN];
__device__ __half  g_Ath[NN*NN];
__device__ float   g_Vx[NN*BB];
__device__ __half  g_zh[2][BB*NN];
__device__ float   g_ns[2][SB][2];   // per-CTA norm slots {d2,n2}, 2-phase
__device__ unsigned g_arrive, g_release;

__device__ __forceinline__ uint32_t smem_u32(const void* p) {
    uint32_t a;
    asm("{ .reg .u64 t; cvta.to.shared.u64 t, %1; cvt.u32.u64 %0, t; }" : "=r"(a) : "l"(p));
    return a;
}
__device__ __forceinline__ void cp16(uint32_t dst, const void* src) {
    asm volatile("cp.async.cg.shared.global [%0], [%1], 16;" :: "r"(dst), "l"(src) : "memory");
}
#define CP_COMMIT() asm volatile("cp.async.commit_group;" ::: "memory")
#define CP_WAIT(n)  asm volatile("cp.async.wait_group %0;" :: "n"(n) : "memory")
__device__ __forceinline__ void ldsm4(uint32_t* r, uint32_t a) {
    asm volatile("ldmatrix.sync.aligned.m8n8.x4.shared.b16 {%0,%1,%2,%3}, [%4];"
                 : "=r"(r[0]), "=r"(r[1]), "=r"(r[2]), "=r"(r[3]) : "r"(a));
}
__device__ __forceinline__ void mma_hf(float* c, const uint32_t* a, uint32_t b0, uint32_t b1) {
    asm volatile("mma.sync.aligned.m16n8k16.row.col.f32.f16.f16.f32 "
                 "{%0,%1,%2,%3}, {%4,%5,%6,%7}, {%8,%9}, {%0,%1,%2,%3};"
                 : "+f"(c[0]), "+f"(c[1]), "+f"(c[2]), "+f"(c[3])
                 : "r"(a[0]), "r"(a[1]), "r"(a[2]), "r"(a[3]), "r"(b0), "r"(b1));
}
__device__ __forceinline__ void sts_v4(uint32_t a, const float* v) {
    asm volatile("st.shared.v4.f32 [%0], {%1,%2,%3,%4};"
                 :: "r"(a), "f"(v[0]), "f"(v[1]), "f"(v[2]), "f"(v[3]) : "memory");
}
__device__ __forceinline__ void lds_v4(float* v, uint32_t a) {
    asm volatile("ld.shared.v4.f32 {%0,%1,%2,%3}, [%4];"
                 : "=f"(v[0]), "=f"(v[1]), "=f"(v[2]), "=f"(v[3]) : "r"(a));
}

// At[i][k] = A[k][i] in fp16, 64x64 tiles; block(0,0) thread 0 resets barrier state
__global__ void __launch_bounds__(256) split_at_kernel(const float* __restrict__ A) {
    __shared__ float t[64][65];
    if (blockIdx.x == 0 && blockIdx.y == 0 && threadIdx.x == 0) {
        g_arrive = 0u; g_release = 0u;
    }
    const int i0 = blockIdx.x * 64, k0 = blockIdx.y * 64;
    const int lx = threadIdx.x & 63, ly = threadIdx.x >> 6;
#pragma unroll
    for (int r = 0; r < 64; r += 4)
        t[ly + r][lx] = A[(long)(k0 + ly + r) * NN + i0 + lx];
    __syncthreads();
#pragma unroll
    for (int r = 0; r < 64; r += 4)
        g_Ath[(long)(i0 + ly + r) * NN + k0 + lx] = __float2half_rn(t[lx][ly + r]);
}

// W = (1-m)I - At At^T + S - S^T  (fp16 mma), symmetric: only bi<=bj blocks.
__global__ void __launch_bounds__(256, 1) build_w_mma_kernel(const float* __restrict__ S,
                                                             const float* __restrict__ m_raw) {
    extern __shared__ __align__(16) char dsm[];
    const uint32_t sbase = (smem_u32(dsm) + 127u) & ~127u;
    const int tid = threadIdx.x, l = tid & 31, warp = tid >> 5;

    int bi = 0, rem = blockIdx.x;
    while (rem >= 16 - bi) { rem -= 16 - bi; bi++; }
    const int bj = bi + rem;
    const int i0 = bi * 128, j0 = bj * 128;

    const int wm = (warp >> 2) * 64, wn = (warp & 3) * 32;
    const int r7 = l & 7;
    const int rowA = wm + r7 + ((l >> 3) & 1) * 8;
    const int kgA = (l >> 4) & 1;
    const int rowBb = wn + r7 + ((l >> 4) & 1) * 8;
    const int kgB = (l >> 3) & 1;

    float c[4][4][4];
#pragma unroll
    for (int f = 0; f < 4; f++)
#pragma unroll
        for (int g = 0; g < 4; g++)
#pragma unroll
            for (int q = 0; q < 4; q++) c[f][g][q] = 0.0f;

#define W_LOAD(stg, k0v) do {                                                 \
    const uint32_t sb_ = sbase + (stg) * WSTG;                                \
    _Pragma("unroll")                                                         \
    for (int rep = 0; rep < 4; rep++) {                                       \
        const int idx_ = tid + rep * 256;                                     \
        const int r_ = idx_ >> 3, c_ = idx_ & 7;                              \
        const uint32_t d_ = (uint32_t)r_ * 128 + ((uint32_t)(c_ ^ (r_ & 7)) << 4); \
        cp16(sb_ + 0*WMAT + d_, g_Ath + (long)(i0 + r_) * NN + (k0v) + c_ * 8); \
        cp16(sb_ + 1*WMAT + d_, g_Ath + (long)(j0 + r_) * NN + (k0v) + c_ * 8); \
    } } while (0)

#pragma unroll
    for (int s = 0; s < WNSTG - 1; s++) { W_LOAD(s, s * WKC); CP_COMMIT(); }

    for (int kc = 0; kc < WNKC; kc++) {
        CP_WAIT(WNSTG - 2);
        __syncthreads();
        if (kc + WNSTG - 1 < WNKC) W_LOAD((kc + WNSTG - 1) % WNSTG, (kc + WNSTG - 1) * WKC);
        CP_COMMIT();
        const uint32_t sb = sbase + (kc % WNSTG) * WSTG;
#pragma unroll
        for (int s4 = 0; s4 < 4; s4++) {
            const int kg0 = s4 * 2;
            const uint32_t swA = (uint32_t)((kg0 + kgA) ^ r7) << 4;
            const uint32_t swB = (uint32_t)((kg0 + kgB) ^ r7) << 4;
            uint32_t ah[4][4], bh[2][4];
#pragma unroll
            for (int f = 0; f < 4; f++)
                ldsm4(ah[f], sb + 0*WMAT + (uint32_t)(rowA + f * 16) * 128 + swA);
#pragma unroll
            for (int g2 = 0; g2 < 2; g2++)
                ldsm4(bh[g2], sb + 1*WMAT + (uint32_t)(rowBb + g2 * 16) * 128 + swB);
#pragma unroll
            for (int f = 0; f < 4; f++)
#pragma unroll
                for (int g2 = 0; g2 < 2; g2++) {
                    mma_hf(c[f][g2*2+0], ah[f], bh[g2][0], bh[g2][1]);
                    mma_hf(c[f][g2*2+1], ah[f], bh[g2][2], bh[g2][3]);
                }
        }
    }
#undef W_LOAD

    const float m = log1pf(expf(m_raw[0]));
    const float omm = 1.0f - m;
#pragma unroll
    for (int f = 0; f < 4; f++)
#pragma unroll
        for (int g = 0; g < 4; g++)
#pragma unroll
            for (int h = 0; h < 2; h++) {
                const int i = i0 + wm + f * 16 + h * 8 + (l >> 2);
                const int j = j0 + wn + g * 8 + (l & 3) * 2;
                const float c0 = c[f][g][h*2+0], c1 = c[f][g][h*2+1];
                float2 sij = *(const float2*)&S[(long)i * NN + j];
                float w0 = -c0 + sij.x - S[(long)j * NN + i];
                float w1 = -c1 + sij.y - S[(long)(j + 1) * NN + i];
                if (i == j) w0 += omm;
                if (i == j + 1) w1 += omm;
                *(__half2*)&g_Wh[(long)i * NN + j] = __floats2half2_rn(w0, w1);
                if (bi != bj) {
                    g_Wh[(long)j * NN + i]       = __float2half_rn(-2.0f * c0 - w0);
                    g_Wh[(long)(j + 1) * NN + i] = __float2half_rn(-2.0f * c1 - w1);
                }
            }
}

#define TMW 64
#define KTW 16
#define PADW 68
__global__ void __launch_bounds__(256) build_vx_kernel(const float* __restrict__ U,
                                                       const float* __restrict__ b,
                                                       const float* __restrict__ x) {
    __shared__ __align__(16) float Us[KTW][PADW];
    __shared__ __align__(16) float Xs[KTW][PADW];
    const int i0 = blockIdx.x * TMW, j0 = blockIdx.y * TMW;
    const int tx = threadIdx.x & 15, ty = threadIdx.x >> 4;
    float acc[4][4];
#pragma unroll
    for (int a = 0; a < 4; a++)
#pragma unroll
        for (int cc = 0; cc < 4; cc++) acc[a][cc] = 0.0f;
    for (int k0 = 0; k0 < DD; k0 += KTW) {
#pragma unroll
        for (int t = threadIdx.x; t < KTW * TMW; t += 256) {
            int rr = t >> 4, cc = t & 15;
            Us[cc][rr] = U[(i0 + rr) * DD + k0 + cc];
            Xs[cc][rr] = x[(j0 + rr) * DD + k0 + cc];
        }
        __syncthreads();
#pragma unroll
        for (int k = 0; k < KTW; k++) {
            float4 av = *(const float4*)&Us[k][ty * 4];
            float4 bv = *(const float4*)&Xs[k][tx * 4];
            float am[4] = {av.x, av.y, av.z, av.w};
            float bn[4] = {bv.x, bv.y, bv.z, bv.w};
#pragma unroll
            for (int mi = 0; mi < 4; mi++)
#pragma unroll
                for (int ni = 0; ni < 4; ni++) acc[mi][ni] += am[mi] * bn[ni];
        }
        __syncthreads();
    }
#pragma unroll
    for (int mi = 0; mi < 4; mi++) {
        const int i = i0 + ty * 4 + mi;
        const float bi = b[i];
#pragma unroll
        for (int ni = 0; ni < 4; ni++)
            g_Vx[i * BB + j0 + tx * 4 + ni] = acc[mi][ni] + bi;
    }
}

__device__ __forceinline__ void grid_barrier(unsigned& gen) {
    __syncthreads();
    if (threadIdx.x == 0) {
        gen++;
        __threadfence();
        unsigned prev = atomicAdd(&g_arrive, 1u);
        if (prev == SB - 1) {
            atomicExch(&g_arrive, 0u);
            __threadfence();
            atomicExch(&g_release, gen);
        } else {
            while (*(volatile unsigned*)&g_release < gen) { }
            __threadfence();
        }
    }
    __syncthreads();
}

// ------ persistent fp16 solver: resident W(k<1152), KC=64 ring, slot norms --
__global__ void __launch_bounds__(256, 1) solve_kernel(float* __restrict__ out) {
    extern __shared__ __align__(16) char dsm[];
    const uint32_t sbase = (smem_u32(dsm) + 127u) & ~127u;
    __shared__ float sredD[8], sredN[8];
    __shared__ int s_stop;

    const int tid = threadIdx.x, l = tid & 31, warp = tid >> 5;
    const int i0 = (blockIdx.x >> 2) * 64, j0 = (blockIdx.x & 3) * 64;
    const int pm = (warp >> 1) & 1;
    const int pn = warp & 1;
    const int ks = warp >> 2;
    const int r7 = l & 7;
    const int rA8 = ((l >> 3) & 1) * 8, selA = (l >> 4) & 1;
    const int rB8 = ((l >> 4) & 1) * 8, selB = (l >> 3) & 1;
    const int rowA0 = pm * 32 + r7 + rA8;
    const int rowB0 = pn * 32 + r7 + rB8;

    // ---- resident W: rows i0..i0+63, k < 1152 (18 chunks of 8KB) ----
#pragma unroll
    for (int rep = 0; rep < 36; rep++) {
        const int idx = tid + rep * 256;
        const int ch = idx >> 9;
        const int rem = idx & 511;
        const int r_ = rem >> 3, c_ = rem & 7;
        cp16(sbase + (uint32_t)ch * SUBB + (uint32_t)r_ * 128 +
                 ((uint32_t)(c_ ^ (r_ & 7)) << 4),
             g_Wh + (long)(i0 + r_) * NN + ch * KC + c_ * 8);
    }
    CP_COMMIT(); CP_WAIT(0); __syncthreads();

    const uint32_t O_RING = sbase + RESB;
    const int gk = ks * 2;

    float zr[2][2][2][2], vx[2][2][2][2];
#pragma unroll
    for (int f = 0; f < 2; f++)
#pragma unroll
        for (int gi = 0; gi < 2; gi++)
#pragma unroll
            for (int h = 0; h < 2; h++) {
                const int i = i0 + pm * 32 + f * 16 + h * 8 + (l >> 2);
                const int j = j0 + pn * 32 + (gk + gi) * 8 + (l & 3) * 2;
                float2 v = *(const float2*)&g_Vx[i * BB + j];
                vx[f][gi][h][0] = v.x; vx[f][gi][h][1] = v.y;
                zr[f][gi][h][0] = 0.0f; zr[f][gi][h][1] = 0.0f;
            }

    const int ld_r0 = tid >> 3, ld_c = tid & 7;
    const uint32_t ld_d0 = (uint32_t)ld_r0 * 128 + ((uint32_t)(ld_c ^ (ld_r0 & 7)) << 4);
    const int ld_r1 = ld_r0 + 32;
    const uint32_t ld_d1 = (uint32_t)ld_r1 * 128 + ((uint32_t)(ld_c ^ (ld_r1 & 7)) << 4);

#define STAGE_LOAD(kcn, zp) do {                                              \
    const int kn_ = (kcn);                                                    \
    const uint32_t st_ = O_RING + (uint32_t)((kn_) % NSTG) * STGB;            \
    const int k0_ = kn_ * KC;                                                 \
    if (kn_ >= RES_SUB) {                                                     \
        cp16(st_ + ld_d0, g_Wh + (long)(i0 + ld_r0) * NN + k0_ + ld_c * 8);   \
        cp16(st_ + ld_d1, g_Wh + (long)(i0 + ld_r1) * NN + k0_ + ld_c * 8);   \
    }                                                                         \
    cp16(st_ + SUBB + ld_d0, (zp) + (long)(j0 + ld_r0) * NN + k0_ + ld_c * 8);\
    cp16(st_ + SUBB + ld_d1, (zp) + (long)(j0 + ld_r1) * NN + k0_ + ld_c * 8);\
    } while (0)

    unsigned gen = 0;
    int cur = 0, it = 0;

    while (1) {
        it++;
        const __half* __restrict__ zp = g_zh[cur];
        float c[2][4][4];
#pragma unroll
        for (int f = 0; f < 2; f++)
#pragma unroll
            for (int g = 0; g < 4; g++)
#pragma unroll
                for (int q = 0; q < 4; q++) c[f][g][q] = 0.0f;

        if (it > 1) {
#pragma unroll
            for (int s = 0; s < NSTG - 1; s++) { STAGE_LOAD(s, zp); CP_COMMIT(); }

            for (int kc = 0; kc < NKC; kc++) {
                CP_WAIT(NSTG - 2);
                __syncthreads();
                if (kc + NSTG - 1 < NKC) STAGE_LOAD(kc + NSTG - 1, zp);
                CP_COMMIT();

                const uint32_t rst = O_RING + (uint32_t)(kc % NSTG) * STGB;
                const uint32_t abase = (kc < RES_SUB)
                    ? sbase + (uint32_t)kc * SUBB
                    : rst;
                const uint32_t bbase = rst + SUBB;
#pragma unroll
                for (int s4 = 0; s4 < 2; s4++) {
                    const int kg0 = (ks * 2 + s4) * 2;
                    const uint32_t swA = (uint32_t)((kg0 + selA) ^ r7) << 4;
                    const uint32_t swB = (uint32_t)((kg0 + selB) ^ r7) << 4;
                    uint32_t ah0[4], ah1[4], bh0[4], bh1[4];
                    ldsm4(ah0, abase + (uint32_t)rowA0 * 128 + swA);
                    ldsm4(ah1, abase + (uint32_t)(rowA0 + 16) * 128 + swA);
                    ldsm4(bh0, bbase + (uint32_t)rowB0 * 128 + swB);
                    ldsm4(bh1, bbase + (uint32_t)(rowB0 + 16) * 128 + swB);
                    mma_hf(c[0][0], ah0, bh0[0], bh0[1]);
                    mma_hf(c[0][1], ah0, bh0[2], bh0[3]);
                    mma_hf(c[0][2], ah0, bh1[0], bh1[1]);
                    mma_hf(c[0][3], ah0, bh1[2], bh1[3]);
                    mma_hf(c[1][0], ah1, bh0[0], bh0[1]);
                    mma_hf(c[1][1], ah1, bh0[2], bh0[3]);
                    mma_hf(c[1][2], ah1, bh1[0], bh1[1]);
                    mma_hf(c[1][3], ah1, bh1[2], bh1[3]);
                }
            }

            // ---- k-split partial exchange (ring reused as buffer) ----
            CP_WAIT(0);
            __syncthreads();
            const uint32_t myslot = O_RING +
                (uint32_t)((((warp & 3) * 2 + ks) * 32 + l)) * 64u;
            const uint32_t prslot = O_RING +
                (uint32_t)((((warp & 3) * 2 + (1 - ks)) * 32 + l)) * 64u;
            const int go = (1 - ks) * 2;
#pragma unroll
            for (int f = 0; f < 2; f++)
#pragma unroll
                for (int gi = 0; gi < 2; gi++)
                    sts_v4(myslot + (uint32_t)(f * 2 + gi) * 16u, c[f][go + gi]);
            __syncthreads();
#pragma unroll
            for (int f = 0; f < 2; f++)
#pragma unroll
                for (int gi = 0; gi < 2; gi++) {
                    float v[4];
                    lds_v4(v, prslot + (uint32_t)(f * 2 + gi) * 16u);
#pragma unroll
                    for (int q = 0; q < 4; q++) c[f][gk + gi][q] += v[q];
                }
        }

        // ---- epilogue ----
        __half* __restrict__ zn = g_zh[cur ^ 1];
        float d2 = 0.0f, n2 = 0.0f;
#pragma unroll
        for (int f = 0; f < 2; f++)
#pragma unroll
            for (int gi = 0; gi < 2; gi++)
#pragma unroll
                for (int h = 0; h < 2; h++) {
                    const int i = i0 + pm * 32 + f * 16 + h * 8 + (l >> 2);
                    const int j = j0 + pn * 32 + (gk + gi) * 8 + (l & 3) * 2;
#pragma unroll
                    for (int p = 0; p < 2; p++) {
                        const float zv = zr[f][gi][h][p];
                        float v = 0.9f * zv +
                                  0.1f * (c[f][gk + gi][h * 2 + p] + vx[f][gi][h][p]);
                        float r = v > 0.0f ? v : 0.0f;
                        zr[f][gi][h][p] = r;
                        zn[(j + p) * NN + i] = __float2half_rn(r);
                        const float dd = r - zv;
                        d2 += dd * dd;
                        n2 += zv * zv;
                    }
                }
#pragma unroll
        for (int off = 16; off; off >>= 1) {
            d2 += __shfl_xor_sync(0xffffffffu, d2, off);
            n2 += __shfl_xor_sync(0xffffffffu, n2, off);
        }
        if (l == 0) { sredD[warp] = d2; sredN[warp] = n2; }
        __syncthreads();
        const int ph = it & 1;
        if (tid == 0) {
            float Dd = 0.0f, Nd = 0.0f;
#pragma unroll
            for (int w = 0; w < 8; w++) { Dd += sredD[w]; Nd += sredN[w]; }
            g_ns[ph][blockIdx.x][0] = Dd;
            g_ns[ph][blockIdx.x][1] = Nd;
        }

        grid_barrier(gen);

        // ---- slot reduction: every CTA computes the stop decision ----
        {
            float d2s = 0.0f, n2s = 0.0f;
            if (tid < SB) {
                float2 sv = *(const float2*)&g_ns[ph][tid][0];
                d2s = sv.x; n2s = sv.y;
            }
#pragma unroll
            for (int off = 16; off; off >>= 1) {
                d2s += __shfl_xor_sync(0xffffffffu, d2s, off);
                n2s += __shfl_xor_sync(0xffffffffu, n2s, off);
            }
            if (l == 0) { sredD[warp] = d2s; sredN[warp] = n2s; }
            __syncthreads();
            if (tid == 0) {
                float Dt = 0.0f, Nt = 0.0f;
#pragma unroll
                for (int w = 0; w < 4; w++) { Dt += sredD[w]; Nt += sredN[w]; }
                const float err = sqrtf(Dt) / (sqrtf(Nt) + 1e-12f);
                s_stop = (it >= MAXIT || err < 1e-4f) ? 1 : 0;
            }
            __syncthreads();
        }
        cur ^= 1;
        if (s_stop) break;
    }
#undef STAGE_LOAD

#pragma unroll
    for (int f = 0; f < 2; f++)
#pragma unroll
        for (int gi = 0; gi < 2; gi++)
#pragma unroll
            for (int h = 0; h < 2; h++) {
                const int i = i0 + pm * 32 + f * 16 + h * 8 + (l >> 2);
                const int j = j0 + pn * 32 + (gk + gi) * 8 + (l & 3) * 2;
                float2 v;
                v.x = zr[f][gi][h][0];
                v.y = zr[f][gi][h][1];
                *(float2*)&out[i * BB + j] = v;
            }
}

extern "C" void kernel_launch(void* const* d_in, const int* in_sizes, int n_in,
                              void* d_out, int out_size) {
    const float* A     = (const float*)d_in[0];
    const float* S     = (const float*)d_in[1];
    const float* m_raw = (const float*)d_in[2];
    const float* U     = (const float*)d_in[3];
    const float* b     = (const float*)d_in[4];
    const float* x     = (const float*)d_in[5];
    float* out = (float*)d_out;

    cudaFuncSetAttribute(solve_kernel, cudaFuncAttributeMaxDynamicSharedMemorySize, DYN_SMEM);
    cudaFuncSetAttribute(build_w_mma_kernel, cudaFuncAttributeMaxDynamicSharedMemorySize, WDYN);

    dim3 gt(NN / 64, NN / 64);
    split_at_kernel<<<gt, 256>>>(A);
    build_w_mma_kernel<<<136, 256, WDYN>>>(S, m_raw);
    dim3 gv(NN / TMW, BB / TMW);
    build_vx_kernel<<<gv, 256>>>(U, b, x);
    solve_kernel<<<SB, 256, DYN_SMEM>>>(out);
}